// round 1
// baseline (speedup 1.0000x reference)
#include <cuda_runtime.h>

// LocalConv2DLayer: res[b,o,h,w] = sum_{c,i,j} m^2,
//   m = clamp(p - l, 0, 1) * clamp(r - p, 0, 1) * 4/(r-l)^2,  p = x[b,c,h+i,w+j]
// l, r are constant over the (i,j) tap dims (broadcast from per-(o[,c]) scalars),
// so res = 5x5 box-sum of S[b,o,h,w] = sum_c s_{o,c}(x[b,c,h,w]).

#define B_N   16
#define IC    3
#define OC    32
#define H_N   64
#define W_N   64
#define KS    5
#define NH    60
#define NW    60
#define NTHR  256

__device__ __forceinline__ float sfun(float v, float l, float r, float n2) {
    float a  = fminf(fmaxf(v - l, 0.0f), 1.0f);   // relu(clip(p-l,-1,1))
    float bb = fminf(fmaxf(r - v, 0.0f), 1.0f);   // relu(clip(r-p,-1,1))
    float t  = a * bb;
    return t * t * n2;                             // (a*b*nc)^2 = (a*b)^2 * nc^2
}

__global__ __launch_bounds__(NTHR, 4)
void localconv2d_kernel(const float* __restrict__ x,
                        const float* __restrict__ lb,
                        const float* __restrict__ rb,
                        float* __restrict__ out)
{
    const int o   = blockIdx.x;   // output channel
    const int b   = blockIdx.y;   // batch
    const int tid = threadIdx.x;

    __shared__ float S [H_N][W_N + 1];   // per-pixel channel-summed s values
    __shared__ float Rh[H_N][NW + 1];    // horizontal 5-tap sums

    // Per-(o,c) bounds: tap-(0,0) element of the broadcast [OC,IC,5,5] arrays.
    float l0[IC], r0[IC], n2[IC];
#pragma unroll
    for (int c = 0; c < IC; ++c) {
        float l = __ldg(lb + (o * IC + c) * (KS * KS));
        float r = __ldg(rb + (o * IC + c) * (KS * KS));
        float d  = r - l;
        float nc = 4.0f / (d * d);
        l0[c] = l; r0[c] = r; n2[c] = nc * nc;
    }

    const float* xb = x + (size_t)b * IC * H_N * W_N;

    // ---- Phase 1: pointwise S[h][w] = sum_c s_{o,c}(x[b,c,h,w]) ----
    // 64*64 = 4096 pixels = 1024 float4 slots; 4 per thread.
#pragma unroll
    for (int k = 0; k < 4; ++k) {
        int idx4 = tid + k * NTHR;        // 0..1023
        int h    = idx4 >> 4;             // 16 float4 per row
        int w4   = (idx4 & 15) << 2;
        float a0 = 0.f, a1 = 0.f, a2 = 0.f, a3 = 0.f;
#pragma unroll
        for (int c = 0; c < IC; ++c) {
            float4 v = *reinterpret_cast<const float4*>(xb + (c * H_N + h) * W_N + w4);
            float l = l0[c], r = r0[c], nn = n2[c];
            a0 += sfun(v.x, l, r, nn);
            a1 += sfun(v.y, l, r, nn);
            a2 += sfun(v.z, l, r, nn);
            a3 += sfun(v.w, l, r, nn);
        }
        S[h][w4 + 0] = a0;
        S[h][w4 + 1] = a1;
        S[h][w4 + 2] = a2;
        S[h][w4 + 3] = a3;
    }
    __syncthreads();

    // ---- Phase 2: horizontal 5-tap sums, Rh[h][w] for h in [0,64), w in [0,60) ----
    // 64*60 = 3840 = 15 * 256 tasks, exact.
#pragma unroll
    for (int k = 0; k < 15; ++k) {
        int idx = tid + k * NTHR;
        int h   = idx / NW;
        int w   = idx - h * NW;
        Rh[h][w] = S[h][w] + S[h][w + 1] + S[h][w + 2] + S[h][w + 3] + S[h][w + 4];
    }
    __syncthreads();

    // ---- Phase 3: vertical 5-tap sums + store, 60*60 = 3600 outputs ----
    float* ob = out + ((size_t)(b * OC + o)) * (NH * NW);
#pragma unroll
    for (int k = 0; k < 15; ++k) {
        int idx = tid + k * NTHR;
        if (idx < NH * NW) {
            int h = idx / NW;
            int w = idx - h * NW;
            float v = Rh[h][w] + Rh[h + 1][w] + Rh[h + 2][w]
                    + Rh[h + 3][w] + Rh[h + 4][w];
            ob[idx] = v;
        }
    }
}

extern "C" void kernel_launch(void* const* d_in, const int* in_sizes, int n_in,
                              void* d_out, int out_size)
{
    const float* x  = (const float*)d_in[0];
    const float* lb = (const float*)d_in[1];
    const float* rb = (const float*)d_in[2];
    float* out      = (float*)d_out;

    dim3 grid(OC, B_N);
    localconv2d_kernel<<<grid, NTHR>>>(x, lb, rb, out);
}